// round 17
// baseline (speedup 1.0000x reference)
#include <cuda_runtime.h>
#include <cuda_fp16.h>
#include <cstdint>

#define B_  2
#define S_  2048
#define D_  1024
#define H_  16
#define DH_ 64
#define M_  (B_*S_)

// fp16 copies of inputs/weights, and projected Q/K/V (allocation-free rule).
__device__ __align__(256) __half g_qh[M_*D_], g_kh[M_*D_], g_vh[M_*D_];
__device__ __align__(256) __half g_Wqh[D_*D_], g_Wkh[D_*D_], g_Wvh[D_*D_];
__device__ __align__(256) __half g_Q[M_*D_], g_K[M_*D_], g_V[M_*D_];

// ---------------------------------------------------------------------------
// Helpers (family-level PTX only)
// ---------------------------------------------------------------------------
__device__ __forceinline__ uint32_t smem_u32(const void* p){
    uint32_t a;
    asm("{ .reg .u64 t; cvta.to.shared.u64 t, %1; cvt.u32.u64 %0, t; }"
        : "=r"(a) : "l"(p));
    return a;
}
__device__ __forceinline__ void cp16(uint32_t dst, const void* src){
    asm volatile("cp.async.cg.shared.global [%0], [%1], 16;"
                 :: "r"(dst), "l"(src) : "memory");
}
__device__ __forceinline__ void cp_commit(){
    asm volatile("cp.async.commit_group;" ::: "memory");
}
__device__ __forceinline__ void cp_wait0(){
    asm volatile("cp.async.wait_group 0;" ::: "memory");
}
__device__ __forceinline__ void cp_wait1(){
    asm volatile("cp.async.wait_group 1;" ::: "memory");
}
// m16n8k16 fp16 mma, fp32 accumulate
__device__ __forceinline__ void mma_f16(float* c, const uint32_t* a, const uint32_t* b){
    asm volatile(
        "mma.sync.aligned.m16n8k16.row.col.f32.f16.f16.f32 "
        "{%0,%1,%2,%3}, {%4,%5,%6,%7}, {%8,%9}, {%0,%1,%2,%3};"
        : "+f"(c[0]), "+f"(c[1]), "+f"(c[2]), "+f"(c[3])
        : "r"(a[0]), "r"(a[1]), "r"(a[2]), "r"(a[3]), "r"(b[0]), "r"(b[1]));
}
__device__ __forceinline__ void ldsm4(uint32_t& r0, uint32_t& r1,
                                      uint32_t& r2, uint32_t& r3, uint32_t a){
    asm volatile("ldmatrix.sync.aligned.m8n8.x4.shared.b16 {%0,%1,%2,%3}, [%4];"
                 : "=r"(r0), "=r"(r1), "=r"(r2), "=r"(r3) : "r"(a));
}
__device__ __forceinline__ void ldsm4t(uint32_t& r0, uint32_t& r1,
                                       uint32_t& r2, uint32_t& r3, uint32_t a){
    asm volatile("ldmatrix.sync.aligned.m8n8.x4.trans.shared.b16 {%0,%1,%2,%3}, [%4];"
                 : "=r"(r0), "=r"(r1), "=r"(r2), "=r"(r3) : "r"(a));
}

// ---------------------------------------------------------------------------
// fp32 -> fp16 pre-convert, single launch (y: 0-2 inputs, 3-5 weights)
// ---------------------------------------------------------------------------
__global__ void cvt_all(const float* __restrict__ q, const float* __restrict__ k,
                        const float* __restrict__ v,
                        const float* __restrict__ wq, const float* __restrict__ wk,
                        const float* __restrict__ wv){
    const int y = blockIdx.y;
    int i = blockIdx.x * blockDim.x + threadIdx.x;
    const float* s;
    __half* d;
    if (y < 3) {
        s = (y == 0) ? q : (y == 1) ? k : v;
        d = (y == 0) ? g_qh : (y == 1) ? g_kh : g_vh;
    } else {
        if (i >= D_*D_/4) return;
        s = (y == 3) ? wq : (y == 4) ? wk : wv;
        d = (y == 3) ? g_Wqh : (y == 4) ? g_Wkh : g_Wvh;
    }
    float4 x = ((const float4*)s)[i];
    ((__half2*)d)[2*i]   = __floats2half2_rn(x.x, x.y);
    ((__half2*)d)[2*i+1] = __floats2half2_rn(x.z, x.w);
}

// ---------------------------------------------------------------------------
// Projection GEMM fp16 m16n8k16 (unchanged — passing since R14)
// ---------------------------------------------------------------------------
#define ASTH 72
#define BSTH 136
#define PA_H (128*ASTH)
#define PB_H (64*BSTH)
#define PBUF_H (PA_H + PB_H)
#define PSMEM_TOT (2*PBUF_H*2)

__global__ __launch_bounds__(256, 2)
void proj_h(const float* __restrict__ bq, const float* __restrict__ bk,
            const float* __restrict__ bv)
{
    extern __shared__ __half smh[];
    const uint32_t smb = smem_u32(smh);
    const int tid = threadIdx.x, wid = tid >> 5, lane = tid & 31;
    const int wm = wid >> 2, wn = wid & 3, grp = lane >> 2, qd = lane & 3;

    const int z = blockIdx.z;
    const __half* A    = (z == 0) ? g_qh  : (z == 1) ? g_kh  : g_vh;
    const __half* W    = (z == 0) ? g_Wqh : (z == 1) ? g_Wkh : g_Wvh;
    const float*  bias = (z == 0) ? bq    : (z == 1) ? bk    : bv;
    __half* C          = (z == 0) ? g_Q   : (z == 1) ? g_K   : g_V;
    const int brow = blockIdx.y * 128, bcol = blockIdx.x * 128;

    auto cp_chunk = [&](int c, int buf){
        const int k0 = c * 64;
        const uint32_t Ab = smb + buf * (PBUF_H * 2);
        const uint32_t Bb = Ab + PA_H * 2;
        #pragma unroll
        for (int l = 0; l < 4; l++) {
            int idx = tid + l * 256;
            int row = idx >> 3, k8 = (idx & 7) * 8;
            cp16(Ab + (row * ASTH + k8) * 2,
                 &A[(size_t)(brow + row) * D_ + k0 + k8]);
        }
        #pragma unroll
        for (int l = 0; l < 4; l++) {
            int idx = tid + l * 256;
            int kk = idx >> 4, n8 = (idx & 15) * 8;
            cp16(Bb + (kk * BSTH + n8) * 2,
                 &W[(size_t)(k0 + kk) * D_ + bcol + n8]);
        }
    };

    float acc[4][4][4];
    #pragma unroll
    for (int i = 0; i < 4; i++)
        #pragma unroll
        for (int j = 0; j < 4; j++)
            #pragma unroll
            for (int r = 0; r < 4; r++) acc[i][j][r] = 0.f;

    const int a_loff = (lane & 15) * ASTH + (lane >> 4) * 8;
    const int b_loff = ((lane & 7) + ((lane >> 3) & 1) * 8) * BSTH
                     + ((lane >= 16) ? 8 : 0);

    cp_chunk(0, 0);
    cp_commit();
    cp_wait0();
    __syncthreads();

    for (int c = 0; c < 16; c++) {
        const int buf = c & 1;
        const uint32_t Ab = smb + buf * (PBUF_H * 2);
        const uint32_t Bb = Ab + PA_H * 2;

        if (c + 1 < 16) { cp_chunk(c + 1, buf ^ 1); cp_commit(); }

        #pragma unroll
        for (int kc = 0; kc < 4; kc++) {
            uint32_t a[4][4];
            #pragma unroll
            for (int i = 0; i < 4; i++)
                ldsm4(a[i][0], a[i][1], a[i][2], a[i][3],
                      Ab + ((wm * 64 + i * 16) * ASTH + kc * 16 + a_loff) * 2);
            uint32_t bfr[4][2];
            #pragma unroll
            for (int ntp = 0; ntp < 2; ntp++)
                ldsm4t(bfr[2*ntp][0], bfr[2*ntp][1],
                       bfr[2*ntp+1][0], bfr[2*ntp+1][1],
                       Bb + ((kc * 16) * BSTH + wn * 32 + ntp * 16 + b_loff) * 2);
            #pragma unroll
            for (int i = 0; i < 4; i++)
                #pragma unroll
                for (int j = 0; j < 4; j++)
                    mma_f16(acc[i][j], a[i], bfr[j]);
        }

        if (c + 1 < 16) cp_wait0();
        __syncthreads();
    }

    #pragma unroll
    for (int j = 0; j < 4; j++) {
        const int c0 = bcol + wn * 32 + j * 8 + 2 * qd;
        const float2 bb = *(const float2*)&bias[c0];
        #pragma unroll
        for (int i = 0; i < 4; i++) {
            const int r0 = brow + wm * 64 + i * 16 + grp;
            *(__half2*)&C[(size_t)r0 * D_ + c0] =
                __floats2half2_rn(acc[i][j][0] + bb.x, acc[i][j][1] + bb.y);
            *(__half2*)&C[(size_t)(r0 + 8) * D_ + c0] =
                __floats2half2_rn(acc[i][j][2] + bb.x, acc[i][j][3] + bb.y);
        }
    }
}

// ---------------------------------------------------------------------------
// Flash attention fp16 v3: 256 thr, 3 CTAs/SM target (24 warps).
// smem trimmed to exactly 72KB (madd gone: mask applied post-exp as a
// multiply — exact, since the masked-column max shift cancels in O/l).
// Q fragments reloaded from resident smem each tile (register pressure).
// Raw-domain max; scale+subtract folded into one fmaf inside exp2.
// ---------------------------------------------------------------------------
#define QSTH 72
#define KSTH 72
#define VSTH 72
#define OFF_Q 0
#define OFF_K (128*QSTH)                 // 9216 halfs
#define OFF_V (OFF_K + 3*64*KSTH)        // +13824
#define OFF_END (OFF_V + 3*64*VSTH)      // 36864 halfs
#define FA_BYTES (OFF_END*2)             // 73728 B = 72KB exactly

__global__ __launch_bounds__(256, 3)
void flash_attn_h(const int* __restrict__ mask, float* __restrict__ out)
{
    extern __shared__ __half smh[];
    const uint32_t smb = smem_u32(smh);

    const int tid = threadIdx.x, w = tid >> 5, lane = tid & 31;
    const int grp = lane >> 2, qd = lane & 3;
    const int bh = blockIdx.y, b = bh >> 4, h = bh & 15;
    const int q0 = blockIdx.x * 128;
    const float SC = 0.03125f * 1.4426950408889634f;   // scale * log2(e)

    const __half* Qb = g_Q + (size_t)b * S_ * D_ + h * DH_;
    const __half* Kb = g_K + (size_t)b * S_ * D_ + h * DH_;
    const __half* Vb = g_V + (size_t)b * S_ * D_ + h * DH_;
    const int* mrow = mask + b * S_;

    auto cp_tile = [&](int it, int buf){
        const int kv0 = it * 64;
        const uint32_t Kd = smb + (OFF_K + buf * 64 * KSTH) * 2;
        const uint32_t Vd = smb + (OFF_V + buf * 64 * VSTH) * 2;
        #pragma unroll
        for (int l = 0; l < 2; l++) {
            int idx = tid + l * 256;
            int row = idx >> 3, c8 = (idx & 7) * 8;
            cp16(Kd + (row * KSTH + c8) * 2, &Kb[(size_t)(kv0 + row) * D_ + c8]);
        }
        #pragma unroll
        for (int l = 0; l < 2; l++) {
            int idx = tid + l * 256;
            int row = idx >> 3, c8 = (idx & 7) * 8;
            cp16(Vd + (row * VSTH + c8) * 2, &Vb[(size_t)(kv0 + row) * D_ + c8]);
        }
    };

    // Stage Q tile (group 0), prefetch kv tiles 0,1 (groups 1,2)
    #pragma unroll
    for (int l = 0; l < 4; l++) {
        int idx = tid + l * 256;
        int row = idx >> 3, c8 = (idx & 7) * 8;
        cp16(smb + (OFF_Q + row * QSTH + c8) * 2,
             &Qb[(size_t)(q0 + row) * D_ + c8]);
    }
    cp_commit();
    cp_tile(0, 0); cp_commit();
    cp_tile(1, 1); cp_commit();

    // per-lane ldmatrix offsets (halfs)
    const int a_loff = (lane & 15) * QSTH + (lane >> 4) * 8;
    const int k_loff = ((lane & 7) + ((lane >= 16) ? 8 : 0)) * KSTH
                     + ((lane >> 3) & 1) * 8;
    const int v_loff = ((lane & 7) + ((lane >> 3) & 1) * 8) * VSTH
                     + ((lane >= 16) ? 8 : 0);

    float o[8][4];
    #pragma unroll
    for (int nt = 0; nt < 8; nt++)
        #pragma unroll
        for (int r = 0; r < 4; r++) o[nt][r] = 0.f;
    float m0 = -1e30f, m1 = -1e30f, l0s = 0.f, l1s = 0.f;

    int b3 = 0;                          // ring buffer index of tile `it`
    for (int it = 0; it < 32; it++) {
        if (it < 31) cp_wait1(); else cp_wait0();
        __syncthreads();                 // tile it (and Q on it=0) visible;
                                         // ring buf (it+2)%3 free
        if (it + 2 < 32) {
            int bn = b3 + 2; if (bn >= 3) bn -= 3;
            cp_tile(it + 2, bn); cp_commit();
        }

        const uint32_t Kcb = smb + (OFF_K + b3 * 64 * KSTH) * 2;
        const uint32_t Vcb = smb + (OFF_V + b3 * 64 * VSTH) * 2;
        const int kv0 = it * 64;

        // ---- Q fragments from resident smem (register-pressure trade) ---
        uint32_t q[4][4];
        #pragma unroll
        for (int kc = 0; kc < 4; kc++)
            ldsm4(q[kc][0], q[kc][1], q[kc][2], q[kc][3],
                  smb + ((w * 16) * QSTH + kc * 16 + a_loff) * 2);

        // ---- S = Q K^T ---------------------------------------------------
        float s[8][4];
        #pragma unroll
        for (int nt = 0; nt < 8; nt++)
            #pragma unroll
            for (int r = 0; r < 4; r++) s[nt][r] = 0.f;

        #pragma unroll
        for (int kc = 0; kc < 4; kc++) {
            #pragma unroll
            for (int ntp = 0; ntp < 4; ntp++) {
                uint32_t r0, r1, r2, r3;
                ldsm4(r0, r1, r2, r3,
                      Kcb + ((ntp * 16) * KSTH + kc * 16 + k_loff) * 2);
                uint32_t bb0[2] = {r0, r1}, bb1[2] = {r2, r3};
                mma_f16(s[2*ntp],   q[kc], bb0);
                mma_f16(s[2*ntp+1], q[kc], bb1);
            }
        }

        // ---- mask bits (int2 per nt; L2-hit, hidden under max chain) ----
        int2 mi[8];
        #pragma unroll
        for (int nt = 0; nt < 8; nt++)
            mi[nt] = *(const int2*)&mrow[kv0 + nt * 8 + 2 * qd];

        // ---- online softmax: raw-domain max, fused scale in exp2 --------
        float mx0 = -1e30f, mx1 = -1e30f;
        #pragma unroll
        for (int nt = 0; nt < 8; nt++) {
            mx0 = fmaxf(mx0, fmaxf(s[nt][0], s[nt][1]));
            mx1 = fmaxf(mx1, fmaxf(s[nt][2], s[nt][3]));
        }
        mx0 = fmaxf(mx0, __shfl_xor_sync(0xffffffffu, mx0, 1));
        mx0 = fmaxf(mx0, __shfl_xor_sync(0xffffffffu, mx0, 2));
        mx1 = fmaxf(mx1, __shfl_xor_sync(0xffffffffu, mx1, 1));
        mx1 = fmaxf(mx1, __shfl_xor_sync(0xffffffffu, mx1, 2));
        const float mn0 = fmaxf(m0, mx0 * SC);
        const float mn1 = fmaxf(m1, mx1 * SC);
        const float al0 = exp2f(m0 - mn0);
        const float al1 = exp2f(m1 - mn1);
        float rs0 = 0.f, rs1 = 0.f;
        uint32_t pa[4][4];
        #pragma unroll
        for (int nt = 0; nt < 8; nt++) {
            const float fbx = (float)mi[nt].x, fby = (float)mi[nt].y;
            float p0 = exp2f(fmaf(s[nt][0], SC, -mn0)) * fbx;
            float p1 = exp2f(fmaf(s[nt][1], SC, -mn0)) * fby;
            float p2 = exp2f(fmaf(s[nt][2], SC, -mn1)) * fbx;
            float p3 = exp2f(fmaf(s[nt][3], SC, -mn1)) * fby;
            rs0 += p0 + p1;
            rs1 += p2 + p3;
            __half2 h01 = __floats2half2_rn(p0, p1);
            __half2 h23 = __floats2half2_rn(p2, p3);
            const int kc = nt >> 1, hi = (nt & 1) * 2;
            pa[kc][hi]     = *reinterpret_cast<uint32_t*>(&h01);
            pa[kc][hi + 1] = *reinterpret_cast<uint32_t*>(&h23);
        }
        l0s = l0s * al0 + rs0;           // deferred cross-lane reduce
        l1s = l1s * al1 + rs1;
        m0 = mn0;
        m1 = mn1;
        #pragma unroll
        for (int nt = 0; nt < 8; nt++) {
            o[nt][0] *= al0; o[nt][1] *= al0;
            o[nt][2] *= al1; o[nt][3] *= al1;
        }

        // ---- O += P V ----------------------------------------------------
        #pragma unroll
        for (int kc = 0; kc < 4; kc++) {
            #pragma unroll
            for (int ntp = 0; ntp < 4; ntp++) {
                uint32_t r0, r1, r2, r3;
                ldsm4t(r0, r1, r2, r3,
                       Vcb + ((kc * 16) * VSTH + ntp * 16 + v_loff) * 2);
                uint32_t bb0[2] = {r0, r1}, bb1[2] = {r2, r3};
                mma_f16(o[2*ntp],   pa[kc], bb0);
                mma_f16(o[2*ntp+1], pa[kc], bb1);
            }
        }
        b3 = (b3 == 2) ? 0 : b3 + 1;
    }

    // ---- final cross-lane l reduce, normalize, write --------------------
    l0s += __shfl_xor_sync(0xffffffffu, l0s, 1);
    l0s += __shfl_xor_sync(0xffffffffu, l0s, 2);
    l1s += __shfl_xor_sync(0xffffffffu, l1s, 1);
    l1s += __shfl_xor_sync(0xffffffffu, l1s, 2);
    const float inv0 = 1.f / l0s;
    const float inv1 = 1.f / l1s;
    const int rl = w * 16 + grp;
    #pragma unroll
    for (int nt = 0; nt < 8; nt++) {
        const int col = h * DH_ + nt * 8 + 2 * qd;
        *(float2*)&out[((size_t)b * S_ + q0 + rl) * D_ + col] =
            make_float2(o[nt][0] * inv0, o[nt][1] * inv0);
        *(float2*)&out[((size_t)b * S_ + q0 + rl + 8) * D_ + col] =
            make_float2(o[nt][2] * inv1, o[nt][3] * inv1);
    }
}

// ---------------------------------------------------------------------------
extern "C" void kernel_launch(void* const* d_in, const int* in_sizes, int n_in,
                              void* d_out, int out_size)
{
    const float* q    = (const float*)d_in[0];
    const float* k    = (const float*)d_in[1];
    const float* v    = (const float*)d_in[2];
    const int*   mask = (const int*)  d_in[3];
    const float* Wq   = (const float*)d_in[4];
    const float* bq   = (const float*)d_in[5];
    const float* Wk   = (const float*)d_in[6];
    const float* bk   = (const float*)d_in[7];
    const float* Wv   = (const float*)d_in[8];
    const float* bv   = (const float*)d_in[9];
    float* out = (float*)d_out;

    (void)in_sizes; (void)n_in; (void)out_size;

    cvt_all<<<dim3(M_*D_/4/256, 6), 256>>>(q, k, v, Wq, Wk, Wv);

    cudaFuncSetAttribute(proj_h,
                         cudaFuncAttributeMaxDynamicSharedMemorySize, PSMEM_TOT);
    dim3 g1(D_/128, M_/128, 3);
    proj_h<<<g1, 256, PSMEM_TOT>>>(bq, bk, bv);

    cudaFuncSetAttribute(flash_attn_h,
                         cudaFuncAttributeMaxDynamicSharedMemorySize, FA_BYTES);
    dim3 g2(S_/128, B_*H_);
    flash_attn_h<<<g2, 256, FA_BYTES>>>(mask, out);
}